// round 3
// baseline (speedup 1.0000x reference)
#include <cuda_runtime.h>
#include <math.h>

#define BB 8
#define NN 4096
#define MM 4096
#define DD 128

#define BK 16
#define PAD  132   // Bs row stride (floats)
#define PAD2 264   // As2 (duplicated) row stride (floats), multiple of 4

typedef unsigned long long u64;

// Scratch (no allocations allowed -> __device__ globals)
__device__ unsigned int g_fwd[BB * MM];        // min over n of clamped squared dist, as uint bits
__device__ float g_x2[BB * NN];
__device__ float g_y2[BB * MM];
__device__ float g_bwd_part[32 * 32];          // per-block backward partial sums
__device__ float g_fwd_part[32];               // stage-A forward partial sums

// ---------------------------------------------------------------------------
__device__ __forceinline__ u64 pack2(float lo, float hi) {
    u64 r;
    asm("mov.b64 %0, {%1,%2};" : "=l"(r) : "f"(lo), "f"(hi));
    return r;
}
__device__ __forceinline__ void unpack2(u64 v, float& lo, float& hi) {
    asm("mov.b64 {%0,%1}, %2;" : "=f"(lo), "=f"(hi) : "l"(v));
}
__device__ __forceinline__ void ffma2(u64& d, u64 a, u64 b) {
    asm("fma.rn.f32x2 %0, %1, %2, %0;" : "+l"(d) : "l"(a), "l"(b));
}

// ---------------------------------------------------------------------------
__global__ void init_kernel() {
    int i = blockIdx.x * blockDim.x + threadIdx.x;
    if (i < BB * MM) g_fwd[i] = 0x7F800000u;   // +inf
}

// One warp per row: sum of squares of 128 floats
__global__ void norms_kernel(const float* __restrict__ X, const float* __restrict__ Y) {
    int w    = (blockIdx.x * blockDim.x + threadIdx.x) >> 5;
    int lane = threadIdx.x & 31;
    const float* p;
    float* dst;
    if (w < BB * NN) {
        p = X + (size_t)w * DD;
        dst = &g_x2[w];
    } else {
        int w2 = w - BB * NN;
        if (w2 >= BB * MM) return;
        p = Y + (size_t)w2 * DD;
        dst = &g_y2[w2];
    }
    float4 v = ((const float4*)p)[lane];
    float s = v.x * v.x + v.y * v.y + v.z * v.z + v.w * v.w;
    #pragma unroll
    for (int o = 16; o; o >>= 1) s += __shfl_xor_sync(0xffffffffu, s, o);
    if (lane == 0) *dst = s;
}

// ---------------------------------------------------------------------------
// Main: per (128n x 128m) tile, loop b=0..7 (flattened with k0), 256 threads,
// 8x8 outputs/thread held as 8x4 packed f32x2 accumulators.
__global__ __launch_bounds__(256, 1) void chamfer_main(const float* __restrict__ X,
                                                       const float* __restrict__ Y) {
    __shared__ float As2[BK * PAD2];          // A tile, each value duplicated
    __shared__ float Bs[BK * PAD];
    __shared__ unsigned int cmin[128];
    __shared__ float red[8];

    const int tid = threadIdx.x;
    const int tx = tid & 15, ty = tid >> 4;
    const int nTile = blockIdx.y * 128;
    const int mTile = blockIdx.x * 128;

    const int lr  = tid >> 2;   // 0..63 : tile row for loads
    const int lc4 = tid & 3;    // 0..3  : float4 column for loads

    const int n0 = ty * 4, n1 = 64 + ty * 4;
    const int m0 = tx * 4, m1 = 64 + tx * 4;

    float bmin[8][8];
    #pragma unroll
    for (int i = 0; i < 8; i++)
        #pragma unroll
        for (int j = 0; j < 8; j++) bmin[i][j] = INFINITY;

    u64 acc2[8][4];
    #pragma unroll
    for (int i = 0; i < 8; i++)
        #pragma unroll
        for (int j = 0; j < 4; j++) acc2[i][j] = 0ull;

    // prefetch registers for the global->smem pipeline
    float4 pva[2], pvb[2];
    {
        const float* Xb = X + ((size_t)0 * NN + nTile) * DD;
        const float* Yb = Y + ((size_t)0 * MM + mTile) * DD;
        #pragma unroll
        for (int h = 0; h < 2; ++h) {
            int r = lr + h * 64;
            pva[h] = *(const float4*)(Xb + (size_t)r * DD + lc4 * 4);
            pvb[h] = *(const float4*)(Yb + (size_t)r * DD + lc4 * 4);
        }
    }

    // 64 steps = 8 batches x 8 k-tiles
    for (int step = 0; step < 64; ++step) {
        const int b  = step >> 3;

        __syncthreads();   // previous consumers done
        #pragma unroll
        for (int h = 0; h < 2; ++h) {
            int r = lr + h * 64;
            float2 d;
            d.x = pva[h].x; d.y = pva[h].x; *(float2*)&As2[(lc4 * 4 + 0) * PAD2 + 2 * r] = d;
            d.x = pva[h].y; d.y = pva[h].y; *(float2*)&As2[(lc4 * 4 + 1) * PAD2 + 2 * r] = d;
            d.x = pva[h].z; d.y = pva[h].z; *(float2*)&As2[(lc4 * 4 + 2) * PAD2 + 2 * r] = d;
            d.x = pva[h].w; d.y = pva[h].w; *(float2*)&As2[(lc4 * 4 + 3) * PAD2 + 2 * r] = d;
            Bs[(lc4 * 4 + 0) * PAD + r] = pvb[h].x;
            Bs[(lc4 * 4 + 1) * PAD + r] = pvb[h].y;
            Bs[(lc4 * 4 + 2) * PAD + r] = pvb[h].z;
            Bs[(lc4 * 4 + 3) * PAD + r] = pvb[h].w;
        }
        __syncthreads();

        // prefetch next step's global data (overlaps with compute below)
        if (step + 1 < 64) {
            int nb  = (step + 1) >> 3;
            int nk0 = ((step + 1) & 7) * BK;
            const float* Xb = X + ((size_t)nb * NN + nTile) * DD;
            const float* Yb = Y + ((size_t)nb * MM + mTile) * DD;
            #pragma unroll
            for (int h = 0; h < 2; ++h) {
                int r = lr + h * 64;
                pva[h] = *(const float4*)(Xb + (size_t)r * DD + nk0 + lc4 * 4);
                pvb[h] = *(const float4*)(Yb + (size_t)r * DD + nk0 + lc4 * 4);
            }
        }

        #pragma unroll
        for (int kk = 0; kk < BK; ++kk) {
            float4 A0 = *(const float4*)&As2[kk * PAD2 + 2 * n0];
            float4 A1 = *(const float4*)&As2[kk * PAD2 + 2 * n0 + 4];
            float4 A2 = *(const float4*)&As2[kk * PAD2 + 2 * n1];
            float4 A3 = *(const float4*)&As2[kk * PAD2 + 2 * n1 + 4];
            float4 b0 = *(const float4*)&Bs[kk * PAD + m0];
            float4 b1 = *(const float4*)&Bs[kk * PAD + m1];
            u64 a2[8];
            a2[0] = pack2(A0.x, A0.y); a2[1] = pack2(A0.z, A0.w);
            a2[2] = pack2(A1.x, A1.y); a2[3] = pack2(A1.z, A1.w);
            a2[4] = pack2(A2.x, A2.y); a2[5] = pack2(A2.z, A2.w);
            a2[6] = pack2(A3.x, A3.y); a2[7] = pack2(A3.z, A3.w);
            u64 b2[4];
            b2[0] = pack2(b0.x, b0.y); b2[1] = pack2(b0.z, b0.w);
            b2[2] = pack2(b1.x, b1.y); b2[3] = pack2(b1.z, b1.w);
            #pragma unroll
            for (int i = 0; i < 8; i++)
                #pragma unroll
                for (int j = 0; j < 4; j++)
                    ffma2(acc2[i][j], a2[i], b2[j]);
        }

        // end of batch b?  -> epilogue
        if ((step & 7) == 7) {
            __syncthreads();
            if (tid < 128) cmin[tid] = 0x7F800000u;
            __syncthreads();

            float rx2[8], ry2[8];
            #pragma unroll
            for (int i = 0; i < 4; i++) {
                rx2[i]     = g_x2[b * NN + nTile + n0 + i];
                rx2[i + 4] = g_x2[b * NN + nTile + n1 + i];
            }
            #pragma unroll
            for (int j = 0; j < 4; j++) {
                ry2[j]     = g_y2[b * MM + mTile + m0 + j];
                ry2[j + 4] = g_y2[b * MM + mTile + m1 + j];
            }

            float colmin[8];
            #pragma unroll
            for (int j = 0; j < 8; j++) colmin[j] = INFINITY;

            #pragma unroll
            for (int i = 0; i < 8; i++) {
                #pragma unroll
                for (int j2 = 0; j2 < 4; j2++) {
                    float lo, hi;
                    unpack2(acc2[i][j2], lo, hi);
                    int jj = j2 * 2;
                    float d2a = fmaf(-2.f, lo, rx2[i] + ry2[jj]);
                    float d2b = fmaf(-2.f, hi, rx2[i] + ry2[jj + 1]);
                    d2a = fmaxf(d2a, 0.f);
                    d2b = fmaxf(d2b, 0.f);
                    bmin[i][jj]     = fminf(bmin[i][jj], d2a);
                    bmin[i][jj + 1] = fminf(bmin[i][jj + 1], d2b);
                    colmin[jj]      = fminf(colmin[jj], d2a);
                    colmin[jj + 1]  = fminf(colmin[jj + 1], d2b);
                    acc2[i][j2] = 0ull;   // reset for next batch
                }
            }

            #pragma unroll
            for (int j = 0; j < 8; j++) {
                int ml = (j < 4) ? (m0 + j) : (m1 + j - 4);
                atomicMin(&cmin[ml], __float_as_uint(colmin[j]));
            }
            __syncthreads();
            if (tid < 128)
                atomicMin(&g_fwd[(size_t)b * MM + mTile + tid], cmin[tid]);
        }
    }

    // backward: min over b complete -> sqrt + block sum
    float bsum = 0.f;
    #pragma unroll
    for (int i = 0; i < 8; i++)
        #pragma unroll
        for (int j = 0; j < 8; j++) bsum += sqrtf(bmin[i][j]);

    #pragma unroll
    for (int o = 16; o; o >>= 1) bsum += __shfl_xor_sync(0xffffffffu, bsum, o);
    if ((tid & 31) == 0) red[tid >> 5] = bsum;
    __syncthreads();
    if (tid < 8) {
        float v = red[tid];
        #pragma unroll
        for (int o = 4; o; o >>= 1) v += __shfl_xor_sync(0xffu, v, o);
        if (tid == 0) g_bwd_part[blockIdx.y * gridDim.x + blockIdx.x] = v;
    }
}

// ---------------------------------------------------------------------------
// Stage A forward reduction: 32 blocks x 256 threads, 1024 elems each.
__global__ void fwd_reduce_kernel() {
    __shared__ float red[8];
    int tid = threadIdx.x;
    int base = blockIdx.x * 1024;
    float s = 0.f;
    #pragma unroll
    for (int r = 0; r < 4; r++)
        s += sqrtf(__uint_as_float(g_fwd[base + r * 256 + tid]));
    #pragma unroll
    for (int o = 16; o; o >>= 1) s += __shfl_xor_sync(0xffffffffu, s, o);
    if ((tid & 31) == 0) red[tid >> 5] = s;
    __syncthreads();
    if (tid < 8) {
        float v = red[tid];
        #pragma unroll
        for (int o = 4; o; o >>= 1) v += __shfl_xor_sync(0xffu, v, o);
        if (tid == 0) g_fwd_part[blockIdx.x] = v;
    }
}

// ---------------------------------------------------------------------------
__global__ void final_kernel(float* __restrict__ out) {
    __shared__ float red[256];
    int tid = threadIdx.x;

    float s1 = (tid < 32) ? g_fwd_part[tid] : 0.f;
    float s2 = 0.f;
    #pragma unroll
    for (int r = 0; r < 4; r++)
        s2 += g_bwd_part[r * 256 + tid];

    red[tid] = s1;
    __syncthreads();
    for (int o = 128; o; o >>= 1) {
        if (tid < o) red[tid] += red[tid + o];
        __syncthreads();
    }
    float fwd_sum = red[0];
    __syncthreads();

    red[tid] = s2;
    __syncthreads();
    for (int o = 128; o; o >>= 1) {
        if (tid < o) red[tid] += red[tid + o];
        __syncthreads();
    }

    if (tid == 0)
        out[0] = fwd_sum / (float)(BB * MM) + red[0] / ((float)NN * (float)MM);
}

// ---------------------------------------------------------------------------
extern "C" void kernel_launch(void* const* d_in, const int* in_sizes, int n_in,
                              void* d_out, int out_size) {
    const float* X = (const float*)d_in[0];   // predicted_set (B,N,D)
    const float* Y = (const float*)d_in[1];   // target_set    (B,M,D)

    init_kernel<<<(BB * MM + 255) / 256, 256>>>();
    norms_kernel<<<(BB * NN + BB * MM) * 32 / 256, 256>>>(X, Y);
    dim3 grid(MM / 128, NN / 128);
    chamfer_main<<<grid, 256>>>(X, Y);
    fwd_reduce_kernel<<<32, 256>>>();
    final_kernel<<<1, 256>>>((float*)d_out);
}

// round 5
// speedup vs baseline: 2.1937x; 2.1937x over previous
#include <cuda_runtime.h>
#include <cuda_fp16.h>
#include <math.h>
#include <stdint.h>

#define BB 8
#define NN 4096
#define MM 4096
#define DD 128

#define BK 16                // k-chunk (2 x k8 mma steps)
#define RS 20                // smem row stride in floats (conflict-free: 20*g+tig distinct mod 32)
#define NSTEPS 64            // BB * (DD/BK)

// ---- device scratch (static; no allocations) ----
__device__ unsigned int g_fwd[BB * MM];
__device__ float g_x2[BB * NN];
__device__ float g_y2[BB * MM];
__device__ float g_bwd_part[1024];
__device__ float g_fwd_part[32];
__device__ float g_xc[BB * NN * DD];   // tf32-rounded copies
__device__ float g_yc[BB * MM * DD];

// ---- helpers ----
__device__ __forceinline__ float cvt_tf32(float x) {
    uint32_t r;
    asm("cvt.rna.tf32.f32 %0, %1;" : "=r"(r) : "f"(x));
    return __uint_as_float(r);
}
__device__ __forceinline__ void cp_async16(void* dst, const float* src) {
    uint32_t d;
    asm("{ .reg .u64 t; cvta.to.shared.u64 t, %1; cvt.u32.u64 %0, t; }" : "=r"(d) : "l"(dst));
    asm volatile("cp.async.cg.shared.global [%0], [%1], 16;" :: "r"(d), "l"(src) : "memory");
}
__device__ __forceinline__ void mma_tf32(float c[4], const uint32_t a[4], const uint32_t b[2]) {
    asm volatile(
        "mma.sync.aligned.m16n8k8.row.col.f32.tf32.tf32.f32 "
        "{%0,%1,%2,%3}, {%4,%5,%6,%7}, {%8,%9}, {%0,%1,%2,%3};"
        : "+f"(c[0]), "+f"(c[1]), "+f"(c[2]), "+f"(c[3])
        : "r"(a[0]), "r"(a[1]), "r"(a[2]), "r"(a[3]), "r"(b[0]), "r"(b[1]));
}

// ---------------------------------------------------------------------------
__global__ void init_kernel() {
    int i = blockIdx.x * blockDim.x + threadIdx.x;
    if (i < BB * MM) g_fwd[i] = 0x7F800000u;
}

// fp32 -> tf32 (round-to-nearest) copies
__global__ void conv_kernel(const float* __restrict__ X, const float* __restrict__ Y) {
    const int Q = BB * NN * DD / 4;
    int i = blockIdx.x * blockDim.x + threadIdx.x;
    if (i < Q) {
        float4 v = ((const float4*)X)[i];
        v.x = cvt_tf32(v.x); v.y = cvt_tf32(v.y);
        v.z = cvt_tf32(v.z); v.w = cvt_tf32(v.w);
        ((float4*)g_xc)[i] = v;
    } else {
        i -= Q;
        float4 v = ((const float4*)Y)[i];
        v.x = cvt_tf32(v.x); v.y = cvt_tf32(v.y);
        v.z = cvt_tf32(v.z); v.w = cvt_tf32(v.w);
        ((float4*)g_yc)[i] = v;
    }
}

__global__ void norms_kernel(const float* __restrict__ X, const float* __restrict__ Y) {
    int w    = (blockIdx.x * blockDim.x + threadIdx.x) >> 5;
    int lane = threadIdx.x & 31;
    const float* p;
    float* dst;
    if (w < BB * NN) {
        p = X + (size_t)w * DD;
        dst = &g_x2[w];
    } else {
        int w2 = w - BB * NN;
        if (w2 >= BB * MM) return;
        p = Y + (size_t)w2 * DD;
        dst = &g_y2[w2];
    }
    float4 v = ((const float4*)p)[lane];
    float s = v.x * v.x + v.y * v.y + v.z * v.z + v.w * v.w;
    #pragma unroll
    for (int o = 16; o; o >>= 1) s += __shfl_xor_sync(0xffffffffu, s, o);
    if (lane == 0) *dst = s;
}

// ---------------------------------------------------------------------------
// Main: CTA = 128n x 128m, 8 warps (2x4), mma.sync m16n8k8 tf32,
// batches looped in-CTA, fused min epilogue.
__global__ __launch_bounds__(256, 1) void chamfer_mma() {
    __shared__ float sA[2][128 * RS];
    __shared__ float sB[2][128 * RS];
    __shared__ float red[8];

    const int tid   = threadIdx.x;
    const int wid   = tid >> 5;
    const int lane  = tid & 31;
    const int g     = lane >> 2;     // row group 0..7
    const int tig   = lane & 3;      // thread in group
    const int mWarp = wid >> 2;      // 0..1 -> rows mWarp*64
    const int nWarp = wid & 3;       // 0..3 -> cols nWarp*32
    const int nTile = blockIdx.y * 128;
    const int mTile = blockIdx.x * 128;

    // cp.async load indices: 2 float4 per thread per tile per stage
    const int lrow = tid >> 2;       // 0..63
    const int lg4  = tid & 3;        // float4 within 16-float chunk

    float c[4][4][4];
    #pragma unroll
    for (int mt = 0; mt < 4; mt++)
        #pragma unroll
        for (int nt = 0; nt < 4; nt++)
            #pragma unroll
            for (int k = 0; k < 4; k++) c[mt][nt][k] = 0.f;

    half2 bwd2[4][4][2];
    const half2 hinf = __floats2half2_rn(65504.f, 65504.f);
    #pragma unroll
    for (int mt = 0; mt < 4; mt++)
        #pragma unroll
        for (int nt = 0; nt < 4; nt++) {
            bwd2[mt][nt][0] = hinf;
            bwd2[mt][nt][1] = hinf;
        }

    // ---- stage loader ----
    auto load_stage = [&](int s) {
        const int b = s >> 3, ch = s & 7;
        const int buf = s & 1;
        const float* xs = g_xc + ((size_t)(b * NN + nTile)) * DD + ch * BK;
        const float* ys = g_yc + ((size_t)(b * MM + mTile)) * DD + ch * BK;
        #pragma unroll
        for (int h = 0; h < 2; ++h) {
            int row = lrow + h * 64;
            cp_async16(&sA[buf][row * RS + lg4 * 4], xs + (size_t)row * DD + lg4 * 4);
            cp_async16(&sB[buf][row * RS + lg4 * 4], ys + (size_t)row * DD + lg4 * 4);
        }
        asm volatile("cp.async.commit_group;" ::: "memory");
    };

    load_stage(0);
    load_stage(1);

    for (int s = 0; s < NSTEPS; ++s) {
        const int buf = s & 1;
        asm volatile("cp.async.wait_group 1;" ::: "memory");
        __syncthreads();

        const float* A = &sA[buf][0];
        const float* B = &sB[buf][0];
        #pragma unroll
        for (int kk = 0; kk < 2; ++kk) {
            uint32_t af[4][4], bf[4][2];
            #pragma unroll
            for (int mt = 0; mt < 4; mt++) {
                int r = mWarp * 64 + mt * 16 + g;
                const uint32_t* p0 = (const uint32_t*)(A + r * RS + kk * 8 + tig);
                const uint32_t* p1 = (const uint32_t*)(A + (r + 8) * RS + kk * 8 + tig);
                af[mt][0] = p0[0];
                af[mt][2] = p0[4];
                af[mt][1] = p1[0];
                af[mt][3] = p1[4];
            }
            #pragma unroll
            for (int nt = 0; nt < 4; nt++) {
                const uint32_t* q =
                    (const uint32_t*)(B + (nWarp * 32 + nt * 8 + g) * RS + kk * 8 + tig);
                bf[nt][0] = q[0];
                bf[nt][1] = q[4];
            }
            #pragma unroll
            for (int mt = 0; mt < 4; mt++)
                #pragma unroll
                for (int nt = 0; nt < 4; nt++)
                    mma_tf32(c[mt][nt], af[mt], bf[nt]);
        }
        __syncthreads();

        if (s + 2 < NSTEPS) load_stage(s + 2);
        else asm volatile("cp.async.commit_group;" ::: "memory");

        if ((s & 7) == 7) {
            // ---- epilogue for batch b ----
            const int b = s >> 3;
            float x2v[4][2], y2v[4][2];
            #pragma unroll
            for (int mt = 0; mt < 4; mt++) {
                int r = b * NN + nTile + mWarp * 64 + mt * 16 + g;
                x2v[mt][0] = g_x2[r];
                x2v[mt][1] = g_x2[r + 8];
            }
            #pragma unroll
            for (int nt = 0; nt < 4; nt++) {
                int col = b * MM + mTile + nWarp * 32 + nt * 8 + 2 * tig;
                y2v[nt][0] = g_y2[col];
                y2v[nt][1] = g_y2[col + 1];
            }

            #pragma unroll
            for (int nt = 0; nt < 4; nt++) {
                float cm0 = INFINITY, cm1 = INFINITY;   // col mins (2 cols) over mt,h
                #pragma unroll
                for (int mt = 0; mt < 4; mt++) {
                    #pragma unroll
                    for (int h = 0; h < 2; h++) {
                        float xy0 = c[mt][nt][2 * h + 0];
                        float xy1 = c[mt][nt][2 * h + 1];
                        float d20 = fmaxf(fmaf(-2.f, xy0, x2v[mt][h] + y2v[nt][0]), 0.f);
                        float d21 = fmaxf(fmaf(-2.f, xy1, x2v[mt][h] + y2v[nt][1]), 0.f);
                        bwd2[mt][nt][h] = __hmin2(bwd2[mt][nt][h], __floats2half2_rn(d20, d21));
                        cm0 = fminf(cm0, d20);
                        cm1 = fminf(cm1, d21);
                        c[mt][nt][2 * h + 0] = 0.f;
                        c[mt][nt][2 * h + 1] = 0.f;
                    }
                }
                // reduce over the 8 row-groups (lanes differing in g: xor 4,8,16)
                #pragma unroll
                for (int o = 4; o <= 16; o <<= 1) {
                    cm0 = fminf(cm0, __shfl_xor_sync(0xffffffffu, cm0, o));
                    cm1 = fminf(cm1, __shfl_xor_sync(0xffffffffu, cm1, o));
                }
                if (g == 0) {
                    int col = b * MM + mTile + nWarp * 32 + nt * 8 + 2 * tig;
                    atomicMin(&g_fwd[col],     __float_as_uint(cm0));
                    atomicMin(&g_fwd[col + 1], __float_as_uint(cm1));
                }
            }
        }
    }

    // ---- backward: min over b complete -> sqrt + block sum ----
    float bsum = 0.f;
    #pragma unroll
    for (int mt = 0; mt < 4; mt++)
        #pragma unroll
        for (int nt = 0; nt < 4; nt++)
            #pragma unroll
            for (int h = 0; h < 2; h++) {
                float2 f = __half22float2(bwd2[mt][nt][h]);
                bsum += sqrtf(f.x) + sqrtf(f.y);
            }
    #pragma unroll
    for (int o = 16; o; o >>= 1) bsum += __shfl_xor_sync(0xffffffffu, bsum, o);
    if (lane == 0) red[wid] = bsum;
    __syncthreads();
    if (tid < 8) {
        float v = red[tid];
        #pragma unroll
        for (int o = 4; o; o >>= 1) v += __shfl_xor_sync(0xffu, v, o);
        if (tid == 0) g_bwd_part[blockIdx.y * gridDim.x + blockIdx.x] = v;
    }
}

// ---------------------------------------------------------------------------
__global__ void fwd_reduce_kernel() {
    __shared__ float red[8];
    int tid = threadIdx.x;
    int base = blockIdx.x * 1024;
    float s = 0.f;
    #pragma unroll
    for (int r = 0; r < 4; r++)
        s += sqrtf(__uint_as_float(g_fwd[base + r * 256 + tid]));
    #pragma unroll
    for (int o = 16; o; o >>= 1) s += __shfl_xor_sync(0xffffffffu, s, o);
    if ((tid & 31) == 0) red[tid >> 5] = s;
    __syncthreads();
    if (tid < 8) {
        float v = red[tid];
        #pragma unroll
        for (int o = 4; o; o >>= 1) v += __shfl_xor_sync(0xffu, v, o);
        if (tid == 0) g_fwd_part[blockIdx.x] = v;
    }
}

__global__ void final_kernel(float* __restrict__ out) {
    __shared__ float red[256];
    int tid = threadIdx.x;

    float s1 = (tid < 32) ? g_fwd_part[tid] : 0.f;
    float s2 = 0.f;
    #pragma unroll
    for (int r = 0; r < 4; r++)
        s2 += g_bwd_part[r * 256 + tid];

    red[tid] = s1;
    __syncthreads();
    for (int o = 128; o; o >>= 1) {
        if (tid < o) red[tid] += red[tid + o];
        __syncthreads();
    }
    float fwd_sum = red[0];
    __syncthreads();

    red[tid] = s2;
    __syncthreads();
    for (int o = 128; o; o >>= 1) {
        if (tid < o) red[tid] += red[tid + o];
        __syncthreads();
    }

    if (tid == 0)
        out[0] = fwd_sum / (float)(BB * MM) + red[0] / ((float)NN * (float)MM);
}

// ---------------------------------------------------------------------------
extern "C" void kernel_launch(void* const* d_in, const int* in_sizes, int n_in,
                              void* d_out, int out_size) {
    const float* X = (const float*)d_in[0];   // predicted_set (B,N,D)
    const float* Y = (const float*)d_in[1];   // target_set    (B,M,D)

    init_kernel<<<(BB * MM + 255) / 256, 256>>>();
    conv_kernel<<<(2 * BB * NN * DD / 4 + 255) / 256, 256>>>(X, Y);
    norms_kernel<<<(BB * NN + BB * MM) * 32 / 256, 256>>>(X, Y);
    dim3 grid(MM / 128, NN / 128);
    chamfer_mma<<<grid, 256>>>();
    fwd_reduce_kernel<<<32, 256>>>();
    final_kernel<<<1, 256>>>((float*)d_out);
}

// round 6
// speedup vs baseline: 3.5284x; 1.6084x over previous
#include <cuda_runtime.h>
#include <cuda_fp16.h>
#include <cuda_bf16.h>
#include <math.h>
#include <stdint.h>

#define BB 8
#define NN 4096
#define MM 4096
#define DD 128

#define BK 32                // k-chunk (2 x k16 mma steps)
#define ST 20                // smem row stride in 32-bit words (16 data + 4 pad)
#define NSTEPS 32            // BB * (DD/BK)

// ---- device scratch (static; no allocations) ----
__device__ unsigned int g_fwd[BB * MM];
__device__ float g_x2[BB * NN];
__device__ float g_y2[BB * MM];
__device__ float g_bwd_part[1024];
__device__ float g_fwd_part[32];
__device__ __nv_bfloat16 g_xc[BB * NN * DD];   // bf16 copies
__device__ __nv_bfloat16 g_yc[BB * MM * DD];

// ---- helpers ----
__device__ __forceinline__ uint32_t pack_bf16(float lo, float hi) {
    uint32_t r;
    asm("cvt.rn.bf16x2.f32 %0, %1, %2;" : "=r"(r) : "f"(hi), "f"(lo));
    return r;
}
__device__ __forceinline__ uint32_t smem_u32(const void* p) {
    uint32_t a;
    asm("{ .reg .u64 t; cvta.to.shared.u64 t, %1; cvt.u32.u64 %0, t; }" : "=r"(a) : "l"(p));
    return a;
}
__device__ __forceinline__ void cp_async16(uint32_t dst, const void* src) {
    asm volatile("cp.async.cg.shared.global [%0], [%1], 16;" :: "r"(dst), "l"(src) : "memory");
}
__device__ __forceinline__ void ldsm4(uint32_t a[4], uint32_t addr) {
    asm volatile("ldmatrix.sync.aligned.m8n8.x4.shared.b16 {%0,%1,%2,%3}, [%4];"
                 : "=r"(a[0]), "=r"(a[1]), "=r"(a[2]), "=r"(a[3]) : "r"(addr));
}
__device__ __forceinline__ void ldsm2(uint32_t a[2], uint32_t addr) {
    asm volatile("ldmatrix.sync.aligned.m8n8.x2.shared.b16 {%0,%1}, [%2];"
                 : "=r"(a[0]), "=r"(a[1]) : "r"(addr));
}
__device__ __forceinline__ void mma_bf16(float c[4], const uint32_t a[4], const uint32_t b[2]) {
    asm volatile(
        "mma.sync.aligned.m16n8k16.row.col.f32.bf16.bf16.f32 "
        "{%0,%1,%2,%3}, {%4,%5,%6,%7}, {%8,%9}, {%0,%1,%2,%3};"
        : "+f"(c[0]), "+f"(c[1]), "+f"(c[2]), "+f"(c[3])
        : "r"(a[0]), "r"(a[1]), "r"(a[2]), "r"(a[3]), "r"(b[0]), "r"(b[1]));
}

// ---------------------------------------------------------------------------
__global__ void init_kernel() {
    int i = blockIdx.x * blockDim.x + threadIdx.x;
    if (i < BB * MM) g_fwd[i] = 0x7F800000u;
}

// fp32 -> bf16 copies; each thread converts 8 floats
__global__ void conv_kernel(const float* __restrict__ X, const float* __restrict__ Y) {
    const int Q = BB * NN * DD / 8;
    int i = blockIdx.x * blockDim.x + threadIdx.x;
    const float4* src;
    uint4* dst;
    int j;
    if (i < Q) { src = (const float4*)X; dst = (uint4*)g_xc; j = i; }
    else       { src = (const float4*)Y; dst = (uint4*)g_yc; j = i - Q; }
    float4 v0 = src[2 * j], v1 = src[2 * j + 1];
    uint4 o;
    o.x = pack_bf16(v0.x, v0.y);
    o.y = pack_bf16(v0.z, v0.w);
    o.z = pack_bf16(v1.x, v1.y);
    o.w = pack_bf16(v1.z, v1.w);
    dst[j] = o;
}

__global__ void norms_kernel(const float* __restrict__ X, const float* __restrict__ Y) {
    int w    = (blockIdx.x * blockDim.x + threadIdx.x) >> 5;
    int lane = threadIdx.x & 31;
    const float* p;
    float* dst;
    if (w < BB * NN) {
        p = X + (size_t)w * DD;
        dst = &g_x2[w];
    } else {
        int w2 = w - BB * NN;
        if (w2 >= BB * MM) return;
        p = Y + (size_t)w2 * DD;
        dst = &g_y2[w2];
    }
    float4 v = ((const float4*)p)[lane];
    float s = v.x * v.x + v.y * v.y + v.z * v.z + v.w * v.w;
    #pragma unroll
    for (int o = 16; o; o >>= 1) s += __shfl_xor_sync(0xffffffffu, s, o);
    if (lane == 0) *dst = s;
}

// ---------------------------------------------------------------------------
// Main: CTA = 128n x 128m, 8 warps (2x4), mma.sync m16n8k16 bf16 + ldmatrix.
__global__ __launch_bounds__(256, 1) void chamfer_mma() {
    __shared__ uint32_t sA[2][128 * ST];
    __shared__ uint32_t sB[2][128 * ST];
    __shared__ float red[8];

    const int tid   = threadIdx.x;
    const int wid   = tid >> 5;
    const int lane  = tid & 31;
    const int g     = lane >> 2;     // row group 0..7
    const int tig   = lane & 3;      // thread in group
    const int mWarp = wid >> 2;      // 0..1 -> rows mWarp*64
    const int nWarp = wid & 3;       // 0..3 -> cols nWarp*32
    const int nTile = blockIdx.y * 128;
    const int mTile = blockIdx.x * 128;

    const uint32_t aB[2] = { smem_u32(&sA[0][0]), smem_u32(&sA[1][0]) };
    const uint32_t bB[2] = { smem_u32(&sB[0][0]), smem_u32(&sB[1][0]) };

    // ldmatrix per-lane address components (byte offsets)
    const uint32_t aOff = (uint32_t)((mWarp * 64 + (lane & 15)) * ST + 4 * (lane >> 4)) * 4;
    const uint32_t bOff = (uint32_t)((nWarp * 32 + (lane & 7)) * ST + 4 * ((lane >> 3) & 1)) * 4;

    // cp.async indices: idx -> (row, chunk); 2 iters per tile
    const int lrow = tid >> 1;          // base row scheme: idx = tid + it*256
    (void)lrow;

    float c[4][4][4];
    #pragma unroll
    for (int mt = 0; mt < 4; mt++)
        #pragma unroll
        for (int nt = 0; nt < 4; nt++)
            #pragma unroll
            for (int k = 0; k < 4; k++) c[mt][nt][k] = 0.f;

    half2 bwd2[4][4][2];
    const half2 hinf = __floats2half2_rn(65504.f, 65504.f);
    #pragma unroll
    for (int mt = 0; mt < 4; mt++)
        #pragma unroll
        for (int nt = 0; nt < 4; nt++) {
            bwd2[mt][nt][0] = hinf;
            bwd2[mt][nt][1] = hinf;
        }

    // ---- stage loader: 128 rows x 32 bf16 (4 x 16B chunks) per tile ----
    auto load_stage = [&](int s) {
        const int b = s >> 2, ch = s & 3;
        const int buf = s & 1;
        const __nv_bfloat16* xs = g_xc + ((size_t)(b * NN + nTile)) * DD + ch * BK;
        const __nv_bfloat16* ys = g_yc + ((size_t)(b * MM + mTile)) * DD + ch * BK;
        #pragma unroll
        for (int it = 0; it < 2; ++it) {
            int idx = tid + it * 256;
            int row = idx >> 2, h = idx & 3;
            uint32_t woff = (uint32_t)(row * ST + 4 * h) * 4;
            cp_async16(aB[buf] + woff, xs + (size_t)row * DD + h * 8);
            cp_async16(bB[buf] + woff, ys + (size_t)row * DD + h * 8);
        }
        asm volatile("cp.async.commit_group;" ::: "memory");
    };

    load_stage(0);
    load_stage(1);

    for (int s = 0; s < NSTEPS; ++s) {
        const int buf = s & 1;
        asm volatile("cp.async.wait_group 1;" ::: "memory");
        __syncthreads();

        #pragma unroll
        for (int kk = 0; kk < 2; ++kk) {
            uint32_t af[4][4], bf[4][2];
            #pragma unroll
            for (int mt = 0; mt < 4; mt++)
                ldsm4(af[mt], aB[buf] + aOff + (uint32_t)(mt * 16 * ST + 8 * kk) * 4);
            #pragma unroll
            for (int nt = 0; nt < 4; nt++)
                ldsm2(bf[nt], bB[buf] + bOff + (uint32_t)(nt * 8 * ST + 8 * kk) * 4);
            #pragma unroll
            for (int mt = 0; mt < 4; mt++)
                #pragma unroll
                for (int nt = 0; nt < 4; nt++)
                    mma_bf16(c[mt][nt], af[mt], bf[nt]);
        }
        __syncthreads();

        if (s + 2 < NSTEPS) load_stage(s + 2);
        else asm volatile("cp.async.commit_group;" ::: "memory");

        if ((s & 3) == 3) {
            // ---- epilogue for batch b ----
            const int b = s >> 2;
            float x2v[4][2], y2v[4][2];
            #pragma unroll
            for (int mt = 0; mt < 4; mt++) {
                int r = b * NN + nTile + mWarp * 64 + mt * 16 + g;
                x2v[mt][0] = g_x2[r];
                x2v[mt][1] = g_x2[r + 8];
            }
            #pragma unroll
            for (int nt = 0; nt < 4; nt++) {
                int col = b * MM + mTile + nWarp * 32 + nt * 8 + 2 * tig;
                y2v[nt][0] = g_y2[col];
                y2v[nt][1] = g_y2[col + 1];
            }

            #pragma unroll
            for (int nt = 0; nt < 4; nt++) {
                float cm0 = INFINITY, cm1 = INFINITY;
                #pragma unroll
                for (int mt = 0; mt < 4; mt++) {
                    #pragma unroll
                    for (int h = 0; h < 2; h++) {
                        float xy0 = c[mt][nt][2 * h + 0];
                        float xy1 = c[mt][nt][2 * h + 1];
                        float d20 = fmaxf(fmaf(-2.f, xy0, x2v[mt][h] + y2v[nt][0]), 0.f);
                        float d21 = fmaxf(fmaf(-2.f, xy1, x2v[mt][h] + y2v[nt][1]), 0.f);
                        bwd2[mt][nt][h] = __hmin2(bwd2[mt][nt][h], __floats2half2_rn(d20, d21));
                        cm0 = fminf(cm0, d20);
                        cm1 = fminf(cm1, d21);
                        c[mt][nt][2 * h + 0] = 0.f;
                        c[mt][nt][2 * h + 1] = 0.f;
                    }
                }
                #pragma unroll
                for (int o = 4; o <= 16; o <<= 1) {
                    cm0 = fminf(cm0, __shfl_xor_sync(0xffffffffu, cm0, o));
                    cm1 = fminf(cm1, __shfl_xor_sync(0xffffffffu, cm1, o));
                }
                if (g == 0) {
                    int col = b * MM + mTile + nWarp * 32 + nt * 8 + 2 * tig;
                    atomicMin(&g_fwd[col],     __float_as_uint(cm0));
                    atomicMin(&g_fwd[col + 1], __float_as_uint(cm1));
                }
            }
        }
    }

    // ---- backward: min over b complete -> sqrt + block sum ----
    float bsum = 0.f;
    #pragma unroll
    for (int mt = 0; mt < 4; mt++)
        #pragma unroll
        for (int nt = 0; nt < 4; nt++)
            #pragma unroll
            for (int h = 0; h < 2; h++) {
                float2 f = __half22float2(bwd2[mt][nt][h]);
                bsum += sqrtf(f.x) + sqrtf(f.y);
            }
    #pragma unroll
    for (int o = 16; o; o >>= 1) bsum += __shfl_xor_sync(0xffffffffu, bsum, o);
    if (lane == 0) red[wid] = bsum;
    __syncthreads();
    if (tid < 8) {
        float v = red[tid];
        #pragma unroll
        for (int o = 4; o; o >>= 1) v += __shfl_xor_sync(0xffu, v, o);
        if (tid == 0) g_bwd_part[blockIdx.y * gridDim.x + blockIdx.x] = v;
    }
}

// ---------------------------------------------------------------------------
__global__ void fwd_reduce_kernel() {
    __shared__ float red[8];
    int tid = threadIdx.x;
    int base = blockIdx.x * 1024;
    float s = 0.f;
    #pragma unroll
    for (int r = 0; r < 4; r++)
        s += sqrtf(__uint_as_float(g_fwd[base + r * 256 + tid]));
    #pragma unroll
    for (int o = 16; o; o >>= 1) s += __shfl_xor_sync(0xffffffffu, s, o);
    if ((tid & 31) == 0) red[tid >> 5] = s;
    __syncthreads();
    if (tid < 8) {
        float v = red[tid];
        #pragma unroll
        for (int o = 4; o; o >>= 1) v += __shfl_xor_sync(0xffu, v, o);
        if (tid == 0) g_fwd_part[blockIdx.x] = v;
    }
}

__global__ void final_kernel(float* __restrict__ out) {
    __shared__ float red[256];
    int tid = threadIdx.x;

    float s1 = (tid < 32) ? g_fwd_part[tid] : 0.f;
    float s2 = 0.f;
    #pragma unroll
    for (int r = 0; r < 4; r++)
        s2 += g_bwd_part[r * 256 + tid];

    red[tid] = s1;
    __syncthreads();
    for (int o = 128; o; o >>= 1) {
        if (tid < o) red[tid] += red[tid + o];
        __syncthreads();
    }
    float fwd_sum = red[0];
    __syncthreads();

    red[tid] = s2;
    __syncthreads();
    for (int o = 128; o; o >>= 1) {
        if (tid < o) red[tid] += red[tid + o];
        __syncthreads();
    }

    if (tid == 0)
        out[0] = fwd_sum / (float)(BB * MM) + red[0] / ((float)NN * (float)MM);
}

// ---------------------------------------------------------------------------
extern "C" void kernel_launch(void* const* d_in, const int* in_sizes, int n_in,
                              void* d_out, int out_size) {
    const float* X = (const float*)d_in[0];   // predicted_set (B,N,D)
    const float* Y = (const float*)d_in[1];   // target_set    (B,M,D)

    init_kernel<<<(BB * MM + 255) / 256, 256>>>();
    conv_kernel<<<(2 * BB * NN * DD / 8 + 255) / 256, 256>>>(X, Y);
    norms_kernel<<<(BB * NN + BB * MM) * 32 / 256, 256>>>(X, Y);
    dim3 grid(MM / 128, NN / 128);
    chamfer_mma<<<grid, 256>>>();
    fwd_reduce_kernel<<<32, 256>>>();
    final_kernel<<<1, 256>>>((float*)d_out);
}